// round 1
// baseline (speedup 1.0000x reference)
#include <cuda_runtime.h>
#include <math.h>

// ---------------- problem constants ----------------
#define BB    2048
#define KK    20
#define DD    128
#define TT    100
#define CC    128
#define TK    40          // 2K tokens
#define HT    20          // token FFN hidden
#define HC    512         // channel FFN hidden
#define M1    (BB*TK)     // 81920 token rows
#define MH    (BB*KK)     // 40960 rows per two-hop half
#define F1    228         // D + T
#define F2    484         // 3D + T

// ---------------- static device scratch ----------------
__device__ float g_feat1[M1 * F1];        // ~74.7 MB
__device__ float g_feat2[2 * MH * F2];    // ~158.6 MB
__device__ float g_tok1 [M1 * CC];        // ~41.9 MB
__device__ float g_tok2 [M1 * CC];        // ~41.9 MB
__device__ float g_ln   [M1 * CC];        // ~41.9 MB
__device__ float g_h    [M1 * HC];        // ~167.8 MB

__device__ __forceinline__ float gelu_f(float x) {
    return 0.5f * x * (1.0f + erff(x * 0.70710678118654752440f));
}

// ---------------- feature builders ----------------
// one-hop: rows b*40+t ; t<20 -> src, t>=20 -> dst. feat = [edge(128) | tenc(100)]
__global__ void build_feat1(const float* __restrict__ et,
                            const int* __restrict__ se, const int* __restrict__ de,
                            const float* __restrict__ dts, const float* __restrict__ dtd,
                            const float* __restrict__ tw, const float* __restrict__ tb) {
    int row = blockIdx.x;
    int b = row / TK, t = row - b * TK;
    int tid = threadIdx.x;
    int eid; float dt;
    if (t < KK) { eid = se[b*KK + t];       dt = dts[b*KK + t]; }
    else        { eid = de[b*KK + t - KK];  dt = dtd[b*KK + t - KK]; }
    float* f = g_feat1 + row * F1;
    f[tid] = et[eid * DD + tid];
    if (tid < TT)
        f[DD + tid] = (eid == 0) ? 0.0f : cosf(dt * tw[tid] + tb[tid]);
}

// two-hop: scratch row = half*MH + b*20 + k. feat = [e1 | e2 | e_base | tenc(dt2, mask=e1)]
__global__ void build_feat2(const float* __restrict__ et,
                            const int* __restrict__ s2e1, const int* __restrict__ s2e2,
                            const int* __restrict__ d2e1, const int* __restrict__ d2e2,
                            const int* __restrict__ se,   const int* __restrict__ de,
                            const float* __restrict__ dt2s, const float* __restrict__ dt2d,
                            const float* __restrict__ tw, const float* __restrict__ tb) {
    int row = blockIdx.x;
    int half = row / MH;
    int rem  = row - half * MH;
    int b = rem / KK, k = rem - b * KK;
    int tid = threadIdx.x;
    int i = b*KK + k;
    int e1, e2, eb; float dt;
    if (half == 0) { e1 = s2e1[i]; e2 = s2e2[i]; eb = se[i]; dt = dt2s[i]; }
    else           { e1 = d2e1[i]; e2 = d2e2[i]; eb = de[i]; dt = dt2d[i]; }
    float* f = g_feat2 + row * F2;
    f[tid]          = et[e1 * DD + tid];
    f[DD + tid]     = et[e2 * DD + tid];
    f[2*DD + tid]   = et[eb * DD + tid];
    if (tid < TT)
        f[3*DD + tid] = (e1 == 0) ? 0.0f : cosf(dt * tw[tid] + tb[tid]);
}

// ---------------- generic fp32 tiled GEMM ----------------
// C[m][n] = A[m][:Kd] @ W[Kd][Ntot] + bias, opt GELU / residual-add / row-scatter.
// BM=64, BN=128, BK=16, 256 threads, thread computes 8x4.
template<bool GELU, bool RESID, bool SCAT>
__global__ __launch_bounds__(256)
void gemm_k(const float* __restrict__ A, int lda, int Kd,
            const float* __restrict__ W, const float* __restrict__ bias,
            float* __restrict__ Cout, int Ntot, int scat_off) {
    __shared__ float sA[16 * 68];   // [k][m], padded
    __shared__ float sW[16 * 128];  // [k][n]
    int tid = threadIdx.x;
    int m0   = blockIdx.y * 64;
    int cblk = blockIdx.x * 128;
    int tx = tid & 31, ty = tid >> 5;
    int c0 = tx * 4, r0 = ty * 8;

    float acc[8][4];
    #pragma unroll
    for (int i = 0; i < 8; i++)
        #pragma unroll
        for (int j = 0; j < 4; j++) acc[i][j] = 0.0f;

    int la_m  = tid >> 2;         // 0..63
    int la_kq = (tid & 3) * 4;    // 0,4,8,12
    int nk = (Kd + 15) >> 4;

    for (int kt = 0; kt < nk; kt++) {
        int kb = kt * 16;
        #pragma unroll
        for (int j = 0; j < 4; j++) {
            int kk = la_kq + j, kg = kb + kk;
            sA[kk * 68 + la_m] = (kg < Kd) ? A[(m0 + la_m) * lda + kg] : 0.0f;
        }
        #pragma unroll
        for (int p = 0; p < 8; p++) {
            int idx = p * 256 + tid;
            int k = idx >> 7, n = idx & 127;
            int kg = kb + k;
            sW[idx] = (kg < Kd) ? W[kg * Ntot + cblk + n] : 0.0f;
        }
        __syncthreads();
        #pragma unroll
        for (int k = 0; k < 16; k++) {
            float4 a0 = *(const float4*)&sA[k * 68 + r0];
            float4 a1 = *(const float4*)&sA[k * 68 + r0 + 4];
            float4 w  = *(const float4*)&sW[k * 128 + c0];
            float av[8] = {a0.x, a0.y, a0.z, a0.w, a1.x, a1.y, a1.z, a1.w};
            float wv[4] = {w.x, w.y, w.z, w.w};
            #pragma unroll
            for (int i = 0; i < 8; i++)
                #pragma unroll
                for (int j = 0; j < 4; j++)
                    acc[i][j] += av[i] * wv[j];
        }
        __syncthreads();
    }

    #pragma unroll
    for (int i = 0; i < 8; i++) {
        int m = m0 + r0 + i;
        int orow;
        if (SCAT) { int b = m / KK; int k = m - b * KK; orow = b * TK + scat_off + k; }
        else      { orow = m; }
        #pragma unroll
        for (int j = 0; j < 4; j++) {
            float v = acc[i][j] + bias[cblk + c0 + j];
            if (GELU) v = gelu_f(v);
            int oi = orow * Ntot + cblk + c0 + j;
            if (RESID) Cout[oi] += v; else Cout[oi] = v;
        }
    }
}

// ---------------- channel LayerNorm (warp per 128-row) ----------------
__global__ void ln_rows(const float* __restrict__ x, float* __restrict__ y,
                        const float* __restrict__ g, const float* __restrict__ b) {
    int warp = (blockIdx.x * blockDim.x + threadIdx.x) >> 5;
    int lane = threadIdx.x & 31;
    float4 v = ((const float4*)(x + (size_t)warp * CC))[lane];
    float s = v.x + v.y + v.z + v.w;
    #pragma unroll
    for (int o = 16; o; o >>= 1) s += __shfl_xor_sync(0xffffffffu, s, o);
    float m = s * (1.0f / 128.0f);
    float d0 = v.x - m, d1 = v.y - m, d2 = v.z - m, d3 = v.w - m;
    float q = d0*d0 + d1*d1 + d2*d2 + d3*d3;
    #pragma unroll
    for (int o = 16; o; o >>= 1) q += __shfl_xor_sync(0xffffffffu, q, o);
    float inv = rsqrtf(q * (1.0f / 128.0f) + 1e-5f);
    float4 gg = ((const float4*)g)[lane];
    float4 bb = ((const float4*)b)[lane];
    float4 o4 = make_float4(d0*inv*gg.x + bb.x, d1*inv*gg.y + bb.y,
                            d2*inv*gg.z + bb.z, d3*inv*gg.w + bb.w);
    ((float4*)(y + (size_t)warp * CC))[lane] = o4;
}

// ---------------- fused token mixing (LN over 40 tokens + 40->20->40 FFN + residual) ----------------
// one thread per (b, c); in-place on x [B,40,128]
__global__ __launch_bounds__(256)
void token_mix(float* __restrict__ x,
               const float* __restrict__ tg, const float* __restrict__ tbq,
               const float* __restrict__ W1, const float* __restrict__ b1,
               const float* __restrict__ W2, const float* __restrict__ b2) {
    __shared__ float sW1[TK*HT], sW2[HT*TK], sb1[HT], sb2[TK], sg[TK], sb[TK];
    int tid = threadIdx.x;
    for (int i = tid; i < TK*HT; i += 256) { sW1[i] = W1[i]; sW2[i] = W2[i]; }
    if (tid < HT) sb1[tid] = b1[tid];
    if (tid < TK) { sb2[tid] = b2[tid]; sg[tid] = tg[tid]; sb[tid] = tbq[tid]; }
    __syncthreads();

    int gidx = blockIdx.x * 256 + tid;
    int b = gidx >> 7, c = gidx & 127;
    float* xp = x + (size_t)b * (TK*CC) + c;

    float xv[TK];
    float s = 0.0f;
    #pragma unroll
    for (int t = 0; t < TK; t++) { xv[t] = xp[t * CC]; s += xv[t]; }
    float m = s * (1.0f / TK);
    float q = 0.0f;
    #pragma unroll
    for (int t = 0; t < TK; t++) { float d = xv[t] - m; q += d * d; }
    float inv = rsqrtf(q * (1.0f / TK) + 1e-5f);
    float y[TK];
    #pragma unroll
    for (int t = 0; t < TK; t++) y[t] = (xv[t] - m) * inv * sg[t] + sb[t];

    float h[HT];
    #pragma unroll
    for (int j = 0; j < HT; j++) {
        float a = sb1[j];
        #pragma unroll
        for (int t = 0; t < TK; t++) a += y[t] * sW1[t * HT + j];
        h[j] = gelu_f(a);
    }
    #pragma unroll
    for (int t = 0; t < TK; t++) {
        float a = sb2[t];
        #pragma unroll
        for (int j = 0; j < HT; j++) a += h[j] * sW2[j * TK + t];
        xp[t * CC] = xv[t] + a;
    }
}

// ---------------- mean over tokens + pcc-softmax combine ----------------
__global__ void combine_k(const float* __restrict__ p1, const float* __restrict__ p2,
                          float* __restrict__ out) {
    int gid = blockIdx.x * 256 + threadIdx.x;
    int b = gid >> 7, c = gid & 127;
    float s1 = 0.0f, s2 = 0.0f;
    #pragma unroll
    for (int t = 0; t < TK; t++) {
        s1 += g_tok1[b * (TK*CC) + t * CC + c];
        s2 += g_tok2[b * (TK*CC) + t * CC + c];
    }
    s1 *= (1.0f / TK);
    s2 *= (1.0f / TK);
    float a = p1[b], d = p2[b];
    float mx = fmaxf(a, d);
    float e1 = expf(a - mx), e2 = expf(d - mx);
    float w1 = e1 / (e1 + e2);
    out[gid] = w1 * s1 + (1.0f - w1) * s2;
}

// ---------------- launcher ----------------
extern "C" void kernel_launch(void* const* d_in, const int* in_sizes, int n_in,
                              void* d_out, int out_size) {
    const float* edge_table = (const float*)d_in[0];
    const int*   src_eids   = (const int*)d_in[1];
    const int*   dst_eids   = (const int*)d_in[2];
    const int*   src2_e1    = (const int*)d_in[3];
    const int*   src2_e2    = (const int*)d_in[4];
    const int*   dst2_e1    = (const int*)d_in[5];
    const int*   dst2_e2    = (const int*)d_in[6];
    const float* dt_src     = (const float*)d_in[7];
    const float* dt_dst     = (const float*)d_in[8];
    const float* dt2_src    = (const float*)d_in[9];
    const float* dt2_dst    = (const float*)d_in[10];
    const float* pcc1       = (const float*)d_in[11];
    const float* pcc2       = (const float*)d_in[12];
    const float* time_w     = (const float*)d_in[13];
    const float* time_b     = (const float*)d_in[14];
    const float* proj_W     = (const float*)d_in[15];
    const float* proj_b     = (const float*)d_in[16];
    const float* eproj_W    = (const float*)d_in[17];
    const float* eproj_b    = (const float*)d_in[18];
    const float* tln_g      = (const float*)d_in[19];
    const float* tln_b      = (const float*)d_in[20];
    const float* tW1        = (const float*)d_in[21];
    const float* tb1        = (const float*)d_in[22];
    const float* tW2        = (const float*)d_in[23];
    const float* tb2        = (const float*)d_in[24];
    const float* cln_g      = (const float*)d_in[25];
    const float* cln_b      = (const float*)d_in[26];
    const float* cW1        = (const float*)d_in[27];
    const float* cb1        = (const float*)d_in[28];
    const float* cW2        = (const float*)d_in[29];
    const float* cb2        = (const float*)d_in[30];
    float* out = (float*)d_out;

    void *p_feat1, *p_feat2, *p_tok1, *p_tok2, *p_ln, *p_h;
    cudaGetSymbolAddress(&p_feat1, g_feat1);
    cudaGetSymbolAddress(&p_feat2, g_feat2);
    cudaGetSymbolAddress(&p_tok1,  g_tok1);
    cudaGetSymbolAddress(&p_tok2,  g_tok2);
    cudaGetSymbolAddress(&p_ln,    g_ln);
    cudaGetSymbolAddress(&p_h,     g_h);
    float* feat1 = (float*)p_feat1;
    float* feat2 = (float*)p_feat2;
    float* tok1  = (float*)p_tok1;
    float* tok2  = (float*)p_tok2;
    float* lnb   = (float*)p_ln;
    float* hb    = (float*)p_h;

    // ---- branch 1: one-hop ----
    build_feat1<<<M1, 128>>>(edge_table, src_eids, dst_eids, dt_src, dt_dst, time_w, time_b);
    gemm_k<false, false, false><<<dim3(1, M1/64), 256>>>(feat1, F1, F1, proj_W, proj_b, tok1, CC, 0);

    for (int i = 0; i < 2; i++) {
        token_mix<<<(BB*CC)/256, 256>>>(tok1, tln_g + i*TK, tln_b + i*TK,
                                        tW1 + i*TK*HT, tb1 + i*HT, tW2 + i*HT*TK, tb2 + i*TK);
        ln_rows<<<M1/8, 256>>>(tok1, lnb, cln_g + i*CC, cln_b + i*CC);
        gemm_k<true,  false, false><<<dim3(4, M1/64), 256>>>(lnb, CC, CC, cW1 + i*CC*HC, cb1 + i*HC, hb, HC, 0);
        gemm_k<false, true,  false><<<dim3(1, M1/64), 256>>>(hb, HC, HC, cW2 + i*HC*CC, cb2 + i*CC, tok1, CC, 0);
    }

    // ---- branch 2: two-hop ----
    build_feat2<<<2*MH, 128>>>(edge_table, src2_e1, src2_e2, dst2_e1, dst2_e2,
                               src_eids, dst_eids, dt2_src, dt2_dst, time_w, time_b);
    for (int half = 0; half < 2; half++) {
        gemm_k<false, false, true><<<dim3(1, MH/64), 256>>>(
            feat2 + half*MH*F2, F2, F2,
            eproj_W + half*F2*CC, eproj_b + half*CC,
            tok2, CC, half*KK);
    }
    for (int i = 2; i < 4; i++) {
        token_mix<<<(BB*CC)/256, 256>>>(tok2, tln_g + i*TK, tln_b + i*TK,
                                        tW1 + i*TK*HT, tb1 + i*HT, tW2 + i*HT*TK, tb2 + i*TK);
        ln_rows<<<M1/8, 256>>>(tok2, lnb, cln_g + i*CC, cln_b + i*CC);
        gemm_k<true,  false, false><<<dim3(4, M1/64), 256>>>(lnb, CC, CC, cW1 + i*CC*HC, cb1 + i*HC, hb, HC, 0);
        gemm_k<false, true,  false><<<dim3(1, M1/64), 256>>>(hb, HC, HC, cW2 + i*HC*CC, cb2 + i*CC, tok2, CC, 0);
    }

    // ---- combine ----
    combine_k<<<(BB*CC)/256, 256>>>(pcc1, pcc2, out);
}

// round 4
// speedup vs baseline: 1.0208x; 1.0208x over previous
#include <cuda_runtime.h>
#include <math.h>

// ---------------- problem constants ----------------
#define BB    2048
#define KK    20
#define DD    128
#define TT    100
#define CC    128
#define TK    40          // 2K tokens
#define HT    20          // token FFN hidden
#define HC    512         // channel FFN hidden
#define M1    (BB*TK)     // 81920 token rows
#define MH    (BB*KK)     // 40960 rows per two-hop half
#define F1    228         // D + T
#define F2    484         // 3D + T

typedef unsigned long long ull;

// ---------------- static device scratch ----------------
__device__ float g_feat1[M1 * F1];
__device__ float g_feat2[2 * MH * F2];
__device__ float g_tok1 [M1 * CC];
__device__ float g_tok2 [M1 * CC];
__device__ float g_ln   [M1 * CC];
__device__ float g_h    [M1 * HC];

__device__ __forceinline__ float gelu_f(float x) {
    return 0.5f * x * (1.0f + erff(x * 0.70710678118654752440f));
}

// packed fp32x2 FMA: d = a*b + d (exact fp32, 2x FFMA throughput on sm_103a)
__device__ __forceinline__ void ffma2(ull &d, ull a, ull b) {
    asm("fma.rn.f32x2 %0, %1, %2, %0;" : "+l"(d) : "l"(a), "l"(b));
}
__device__ __forceinline__ ull splat2(float x) {
    ull r; asm("mov.b64 %0, {%1, %1};" : "=l"(r) : "f"(x)); return r;
}

// ---------------- feature builders ----------------
__global__ void build_feat1(const float* __restrict__ et,
                            const int* __restrict__ se, const int* __restrict__ de,
                            const float* __restrict__ dts, const float* __restrict__ dtd,
                            const float* __restrict__ tw, const float* __restrict__ tb) {
    int row = blockIdx.x;
    int b = row / TK, t = row - b * TK;
    int tid = threadIdx.x;
    int eid; float dt;
    if (t < KK) { eid = se[b*KK + t];       dt = dts[b*KK + t]; }
    else        { eid = de[b*KK + t - KK];  dt = dtd[b*KK + t - KK]; }
    float* f = g_feat1 + row * F1;
    f[tid] = et[(size_t)eid * DD + tid];
    if (tid < TT)
        f[DD + tid] = (eid == 0) ? 0.0f : cosf(dt * tw[tid] + tb[tid]);
}

__global__ void build_feat2(const float* __restrict__ et,
                            const int* __restrict__ s2e1, const int* __restrict__ s2e2,
                            const int* __restrict__ d2e1, const int* __restrict__ d2e2,
                            const int* __restrict__ se,   const int* __restrict__ de,
                            const float* __restrict__ dt2s, const float* __restrict__ dt2d,
                            const float* __restrict__ tw, const float* __restrict__ tb) {
    int row = blockIdx.x;
    int half = row / MH;
    int rem  = row - half * MH;
    int b = rem / KK, k = rem - b * KK;
    int tid = threadIdx.x;
    int i = b*KK + k;
    int e1, e2, eb; float dt;
    if (half == 0) { e1 = s2e1[i]; e2 = s2e2[i]; eb = se[i]; dt = dt2s[i]; }
    else           { e1 = d2e1[i]; e2 = d2e2[i]; eb = de[i]; dt = dt2d[i]; }
    float* f = g_feat2 + (size_t)row * F2;
    f[tid]          = et[(size_t)e1 * DD + tid];
    f[DD + tid]     = et[(size_t)e2 * DD + tid];
    f[2*DD + tid]   = et[(size_t)eb * DD + tid];
    if (tid < TT)
        f[3*DD + tid] = (e1 == 0) ? 0.0f : cosf(dt * tw[tid] + tb[tid]);
}

// ---------------- fp32x2 tiled GEMM ----------------
// C[m][n] = A[m][:Kd] @ W[Kd][Ntot] + bias, opt GELU / residual / row-scatter.
// BM=128, BN=128, BK=16, 256 threads, 8x8 per thread (4+4 split), f32x2 accum.
template<bool GELU, bool RESID, bool SCAT>
__global__ __launch_bounds__(256)
void gemm_k(const float* __restrict__ A, int Kd,
            const float* __restrict__ W, const float* __restrict__ bias,
            float* __restrict__ Cout, int Ntot, int scat_off) {
    __shared__ float sA[16 * 132];   // [k][m], pitch 132
    __shared__ float sW[16 * 128];   // [k][n]
    int tid = threadIdx.x;
    int m0 = blockIdx.y * 128;
    int n0 = blockIdx.x * 128;
    int tx = tid & 15, ty = tid >> 4;

    int ar  = tid >> 1;              // A row handled by this thread (0..127)
    int aq0 = (tid & 1) * 2;         // first float4 index within the 16-wide k slab
    const float* Arow = A + (size_t)(m0 + ar) * Kd;

    int nk = (Kd + 15) >> 4;

    float4 pa[2], pw[2];

    auto loadA = [&](int kb) {
        #pragma unroll
        for (int q = 0; q < 2; q++) {
            int kg = kb + (aq0 + q) * 4;
            if (kg + 3 < Kd) {
                pa[q] = *(const float4*)(Arow + kg);
            } else {
                float4 v = make_float4(0.f, 0.f, 0.f, 0.f);
                if (kg + 0 < Kd) v.x = Arow[kg + 0];
                if (kg + 1 < Kd) v.y = Arow[kg + 1];
                if (kg + 2 < Kd) v.z = Arow[kg + 2];
                if (kg + 3 < Kd) v.w = Arow[kg + 3];
                pa[q] = v;
            }
        }
    };
    auto loadW = [&](int kb) {
        #pragma unroll
        for (int p = 0; p < 2; p++) {
            int idx = p * 256 + tid;
            int k = idx >> 5, n4 = idx & 31;
            int kg = kb + k;
            pw[p] = (kg < Kd) ? *(const float4*)(W + (size_t)kg * Ntot + n0 + n4 * 4)
                              : make_float4(0.f, 0.f, 0.f, 0.f);
        }
    };
    auto storeTiles = [&]() {
        #pragma unroll
        for (int q = 0; q < 2; q++) {
            int kk = (aq0 + q) * 4;
            sA[(kk + 0) * 132 + ar] = pa[q].x;
            sA[(kk + 1) * 132 + ar] = pa[q].y;
            sA[(kk + 2) * 132 + ar] = pa[q].z;
            sA[(kk + 3) * 132 + ar] = pa[q].w;
        }
        #pragma unroll
        for (int p = 0; p < 2; p++) {
            int idx = p * 256 + tid;
            int k = idx >> 5, n4 = idx & 31;
            *(float4*)(sW + k * 128 + n4 * 4) = pw[p];
        }
    };

    ull acc[8][4];
    #pragma unroll
    for (int i = 0; i < 8; i++)
        #pragma unroll
        for (int j = 0; j < 4; j++) acc[i][j] = 0ull;

    loadA(0); loadW(0);
    storeTiles();
    __syncthreads();

    for (int kt = 0; kt < nk; kt++) {
        bool more = (kt + 1 < nk);
        if (more) { loadA((kt + 1) * 16); loadW((kt + 1) * 16); }
        #pragma unroll
        for (int k = 0; k < 16; k++) {
            float4 a0 = *(const float4*)&sA[k * 132 + ty * 4];
            float4 a1 = *(const float4*)&sA[k * 132 + 64 + ty * 4];
            ulonglong2 w0 = *(const ulonglong2*)&sW[k * 128 + tx * 4];
            ulonglong2 w1 = *(const ulonglong2*)&sW[k * 128 + 64 + tx * 4];
            ull av[8] = { splat2(a0.x), splat2(a0.y), splat2(a0.z), splat2(a0.w),
                          splat2(a1.x), splat2(a1.y), splat2(a1.z), splat2(a1.w) };
            ull wv[4] = { w0.x, w0.y, w1.x, w1.y };
            #pragma unroll
            for (int i = 0; i < 8; i++)
                #pragma unroll
                for (int j = 0; j < 4; j++)
                    ffma2(acc[i][j], av[i], wv[j]);
        }
        __syncthreads();
        if (more) { storeTiles(); __syncthreads(); }
    }

    // epilogue
    #pragma unroll
    for (int i = 0; i < 8; i++) {
        int mr = (i < 4) ? (ty * 4 + i) : (64 + ty * 4 + (i - 4));
        int m = m0 + mr;
        int orow;
        if (SCAT) { int b = m / KK; int kk = m - b * KK; orow = b * TK + scat_off + kk; }
        else      { orow = m; }
        #pragma unroll
        for (int j = 0; j < 4; j++) {
            int c = n0 + ((j < 2) ? (tx * 4 + j * 2) : (64 + tx * 4 + (j - 2) * 2));
            float2 v = *(float2*)&acc[i][j];
            float2 bb = *(const float2*)(bias + c);
            float v0 = v.x + bb.x, v1 = v.y + bb.y;
            if (GELU) { v0 = gelu_f(v0); v1 = gelu_f(v1); }
            float2* op = (float2*)(Cout + (size_t)orow * Ntot + c);
            if (RESID) { float2 o = *op; o.x += v0; o.y += v1; *op = o; }
            else       { *op = make_float2(v0, v1); }
        }
    }
}

// ---------------- channel LayerNorm (warp per 128-row) ----------------
__global__ void ln_rows(const float* __restrict__ x, float* __restrict__ y,
                        const float* __restrict__ g, const float* __restrict__ b) {
    int warp = (blockIdx.x * blockDim.x + threadIdx.x) >> 5;
    int lane = threadIdx.x & 31;
    float4 v = ((const float4*)(x + (size_t)warp * CC))[lane];
    float s = v.x + v.y + v.z + v.w;
    #pragma unroll
    for (int o = 16; o; o >>= 1) s += __shfl_xor_sync(0xffffffffu, s, o);
    float m = s * (1.0f / 128.0f);
    float d0 = v.x - m, d1 = v.y - m, d2 = v.z - m, d3 = v.w - m;
    float q = d0*d0 + d1*d1 + d2*d2 + d3*d3;
    #pragma unroll
    for (int o = 16; o; o >>= 1) q += __shfl_xor_sync(0xffffffffu, q, o);
    float inv = rsqrtf(q * (1.0f / 128.0f) + 1e-5f);
    float4 gg = ((const float4*)g)[lane];
    float4 bb = ((const float4*)b)[lane];
    float4 o4 = make_float4(d0*inv*gg.x + bb.x, d1*inv*gg.y + bb.y,
                            d2*inv*gg.z + bb.z, d3*inv*gg.w + bb.w);
    ((float4*)(y + (size_t)warp * CC))[lane] = o4;
}

// ---------------- fused token mixing ----------------
__global__ __launch_bounds__(256)
void token_mix(float* __restrict__ x,
               const float* __restrict__ tg, const float* __restrict__ tbq,
               const float* __restrict__ W1, const float* __restrict__ b1,
               const float* __restrict__ W2, const float* __restrict__ b2) {
    __shared__ float sW1[TK*HT], sW2[HT*TK], sb1[HT], sb2[TK], sg[TK], sb[TK];
    int tid = threadIdx.x;
    for (int i = tid; i < TK*HT; i += 256) { sW1[i] = W1[i]; sW2[i] = W2[i]; }
    if (tid < HT) sb1[tid] = b1[tid];
    if (tid < TK) { sb2[tid] = b2[tid]; sg[tid] = tg[tid]; sb[tid] = tbq[tid]; }
    __syncthreads();

    int gidx = blockIdx.x * 256 + tid;
    int b = gidx >> 7, c = gidx & 127;
    float* xp = x + (size_t)b * (TK*CC) + c;

    float xv[TK];
    float s = 0.0f;
    #pragma unroll
    for (int t = 0; t < TK; t++) { xv[t] = xp[t * CC]; s += xv[t]; }
    float m = s * (1.0f / TK);
    float q = 0.0f;
    #pragma unroll
    for (int t = 0; t < TK; t++) { float d = xv[t] - m; q += d * d; }
    float inv = rsqrtf(q * (1.0f / TK) + 1e-5f);
    float y[TK];
    #pragma unroll
    for (int t = 0; t < TK; t++) y[t] = (xv[t] - m) * inv * sg[t] + sb[t];

    float h[HT];
    #pragma unroll
    for (int j = 0; j < HT; j++) {
        float a = sb1[j];
        #pragma unroll
        for (int t = 0; t < TK; t++) a += y[t] * sW1[t * HT + j];
        h[j] = gelu_f(a);
    }
    #pragma unroll
    for (int t = 0; t < TK; t++) {
        float a = sb2[t];
        #pragma unroll
        for (int j = 0; j < HT; j++) a += h[j] * sW2[j * TK + t];
        xp[t * CC] = xv[t] + a;
    }
}

// ---------------- mean over tokens + pcc-softmax combine ----------------
__global__ void combine_k(const float* __restrict__ p1, const float* __restrict__ p2,
                          float* __restrict__ out) {
    int gid = blockIdx.x * 256 + threadIdx.x;
    int b = gid >> 7, c = gid & 127;
    float s1 = 0.0f, s2 = 0.0f;
    #pragma unroll
    for (int t = 0; t < TK; t++) {
        s1 += g_tok1[b * (TK*CC) + t * CC + c];
        s2 += g_tok2[b * (TK*CC) + t * CC + c];
    }
    s1 *= (1.0f / TK);
    s2 *= (1.0f / TK);
    float a = p1[b], d = p2[b];
    float mx = fmaxf(a, d);
    float e1 = expf(a - mx), e2 = expf(d - mx);
    float w1 = e1 / (e1 + e2);
    out[gid] = w1 * s1 + (1.0f - w1) * s2;
}

// ---------------- launcher ----------------
extern "C" void kernel_launch(void* const* d_in, const int* in_sizes, int n_in,
                              void* d_out, int out_size) {
    const float* edge_table = (const float*)d_in[0];
    const int*   src_eids   = (const int*)d_in[1];
    const int*   dst_eids   = (const int*)d_in[2];
    const int*   src2_e1    = (const int*)d_in[3];
    const int*   src2_e2    = (const int*)d_in[4];
    const int*   dst2_e1    = (const int*)d_in[5];
    const int*   dst2_e2    = (const int*)d_in[6];
    const float* dt_src     = (const float*)d_in[7];
    const float* dt_dst     = (const float*)d_in[8];
    const float* dt2_src    = (const float*)d_in[9];
    const float* dt2_dst    = (const float*)d_in[10];
    const float* pcc1       = (const float*)d_in[11];
    const float* pcc2       = (const float*)d_in[12];
    const float* time_w     = (const float*)d_in[13];
    const float* time_b     = (const float*)d_in[14];
    const float* proj_W     = (const float*)d_in[15];
    const float* proj_b     = (const float*)d_in[16];
    const float* eproj_W    = (const float*)d_in[17];
    const float* eproj_b    = (const float*)d_in[18];
    const float* tln_g      = (const float*)d_in[19];
    const float* tln_b      = (const float*)d_in[20];
    const float* tW1        = (const float*)d_in[21];
    const float* tb1        = (const float*)d_in[22];
    const float* tW2        = (const float*)d_in[23];
    const float* tb2        = (const float*)d_in[24];
    const float* cln_g      = (const float*)d_in[25];
    const float* cln_b      = (const float*)d_in[26];
    const float* cW1        = (const float*)d_in[27];
    const float* cb1        = (const float*)d_in[28];
    const float* cW2        = (const float*)d_in[29];
    const float* cb2        = (const float*)d_in[30];
    float* out = (float*)d_out;

    void *p_feat1, *p_feat2, *p_tok1, *p_tok2, *p_ln, *p_h;
    cudaGetSymbolAddress(&p_feat1, g_feat1);
    cudaGetSymbolAddress(&p_feat2, g_feat2);
    cudaGetSymbolAddress(&p_tok1,  g_tok1);
    cudaGetSymbolAddress(&p_tok2,  g_tok2);
    cudaGetSymbolAddress(&p_ln,    g_ln);
    cudaGetSymbolAddress(&p_h,     g_h);
    float* feat1 = (float*)p_feat1;
    float* feat2 = (float*)p_feat2;
    float* tok1  = (float*)p_tok1;
    float* tok2  = (float*)p_tok2;
    float* lnb   = (float*)p_ln;
    float* hb    = (float*)p_h;

    // ---- branch 1: one-hop ----
    build_feat1<<<M1, 128>>>(edge_table, src_eids, dst_eids, dt_src, dt_dst, time_w, time_b);
    gemm_k<false, false, false><<<dim3(1, M1/128), 256>>>(feat1, F1, proj_W, proj_b, tok1, CC, 0);

    for (int i = 0; i < 2; i++) {
        token_mix<<<(BB*CC)/256, 256>>>(tok1, tln_g + i*TK, tln_b + i*TK,
                                        tW1 + i*TK*HT, tb1 + i*HT, tW2 + i*HT*TK, tb2 + i*TK);
        ln_rows<<<M1/8, 256>>>(tok1, lnb, cln_g + i*CC, cln_b + i*CC);
        gemm_k<true,  false, false><<<dim3(4, M1/128), 256>>>(lnb, CC, cW1 + i*CC*HC, cb1 + i*HC, hb, HC, 0);
        gemm_k<false, true,  false><<<dim3(1, M1/128), 256>>>(hb, HC, cW2 + i*HC*CC, cb2 + i*CC, tok1, CC, 0);
    }

    // ---- branch 2: two-hop ----
    build_feat2<<<2*MH, 128>>>(edge_table, src2_e1, src2_e2, dst2_e1, dst2_e2,
                               src_eids, dst_eids, dt2_src, dt2_dst, time_w, time_b);
    for (int half = 0; half < 2; half++) {
        gemm_k<false, false, true><<<dim3(1, MH/128), 256>>>(
            feat2 + (size_t)half*MH*F2, F2,
            eproj_W + half*F2*CC, eproj_b + half*CC,
            tok2, CC, half*KK);
    }
    for (int i = 2; i < 4; i++) {
        token_mix<<<(BB*CC)/256, 256>>>(tok2, tln_g + i*TK, tln_b + i*TK,
                                        tW1 + i*TK*HT, tb1 + i*HT, tW2 + i*HT*TK, tb2 + i*TK);
        ln_rows<<<M1/8, 256>>>(tok2, lnb, cln_g + i*CC, cln_b + i*CC);
        gemm_k<true,  false, false><<<dim3(4, M1/128), 256>>>(lnb, CC, cW1 + i*CC*HC, cb1 + i*HC, hb, HC, 0);
        gemm_k<false, true,  false><<<dim3(1, M1/128), 256>>>(hb, HC, cW2 + i*HC*CC, cb2 + i*CC, tok2, CC, 0);
    }

    // ---- combine ----
    combine_k<<<(BB*CC)/256, 256>>>(pcc1, pcc2, out);
}